// round 1
// baseline (speedup 1.0000x reference)
#include <cuda_runtime.h>
#include <cstdint>
#include <cstddef>

// Problem dims (fixed by the reference)
#define B_DIM   128
#define L_DIM   512
#define IN_DIM  512
#define MEM     1024
#define NOUT    2048
#define M_DIM   (B_DIM * L_DIM)   // 65536 rows

// ---------------------------------------------------------------------------
// Scratch: in_emb post-transform. Column o<1024 holds soma_bias = 5*tanh(c1/5),
// column o>=1024 holds i_o (raw emb + bias). 512 MB __device__ global (allowed;
// no runtime allocation).
// ---------------------------------------------------------------------------
__device__ float g_emb[(size_t)M_DIM * NOUT];

// ---------------------------------------------------------------------------
// Packed f32x2 helpers (Blackwell FFMA2 — only reachable via PTX fma.rn.f32x2)
// ---------------------------------------------------------------------------
__device__ __forceinline__ unsigned long long pack2(float lo, float hi) {
    unsigned long long r;
    asm("mov.b64 %0, {%1, %2};" : "=l"(r) : "f"(lo), "f"(hi));
    return r;
}
__device__ __forceinline__ void unpack2(unsigned long long v, float& lo, float& hi) {
    asm("mov.b64 {%0, %1}, %2;" : "=f"(lo), "=f"(hi) : "l"(v));
}
__device__ __forceinline__ void fma2(unsigned long long& d,
                                     unsigned long long a, unsigned long long b) {
    asm("fma.rn.f32x2 %0, %1, %2, %0;" : "+l"(d) : "l"(a), "l"(b));
}

// ---------------------------------------------------------------------------
// Phase 1: C[m][o] = sum_k u[m][k] * W[o][k] + bias[o], fused epilogue.
// Tile: 128x128x16, 256 threads, 8x8 per-thread microtile, f32x2 accumulators.
// Grid: (NOUT/128 = 16, M/128 = 512).
// ---------------------------------------------------------------------------
#define BM 128
#define BN 128
#define BK 16

__global__ __launch_bounds__(256)
void gemm_emb_kernel(const float* __restrict__ A,     // u   [M][512]
                     const float* __restrict__ W,     // W   [2048][512]
                     const float* __restrict__ bias)  // b   [2048]
{
    __shared__ float As[BK][BM];
    __shared__ float Bs[BK][BN + 4];   // pad to soften LDS bank conflicts

    const int bn  = blockIdx.x;
    const int bm  = blockIdx.y;
    const int tid = threadIdx.x;
    const int tx  = tid & 15;
    const int ty  = tid >> 4;
    const int tm  = ty * 8;
    const int tn  = tx * 8;

    const float* Ab = A + (size_t)bm * BM * IN_DIM;
    const float* Wb = W + (size_t)bn * BN * IN_DIM;

    unsigned long long c2[8][4];
#pragma unroll
    for (int i = 0; i < 8; i++)
#pragma unroll
        for (int j = 0; j < 4; j++) c2[i][j] = 0ull;

    for (int k0 = 0; k0 < IN_DIM; k0 += BK) {
        // Load A tile (128x16) — 512 float4, 2 per thread, stored transposed.
#pragma unroll
        for (int i = 0; i < 2; i++) {
            int id  = tid * 2 + i;      // 0..511
            int row = id >> 2;
            int k4  = id & 3;
            float4 v = *(const float4*)(Ab + (size_t)row * IN_DIM + k0 + k4 * 4);
            As[k4 * 4 + 0][row] = v.x;
            As[k4 * 4 + 1][row] = v.y;
            As[k4 * 4 + 2][row] = v.z;
            As[k4 * 4 + 3][row] = v.w;
        }
        // Load W tile (128x16), transposed.
#pragma unroll
        for (int i = 0; i < 2; i++) {
            int id  = tid * 2 + i;
            int row = id >> 2;
            int k4  = id & 3;
            float4 v = *(const float4*)(Wb + (size_t)row * IN_DIM + k0 + k4 * 4);
            Bs[k4 * 4 + 0][row] = v.x;
            Bs[k4 * 4 + 1][row] = v.y;
            Bs[k4 * 4 + 2][row] = v.z;
            Bs[k4 * 4 + 3][row] = v.w;
        }
        __syncthreads();

#pragma unroll
        for (int kk = 0; kk < BK; kk++) {
            float4 a0 = *(const float4*)&As[kk][tm];
            float4 a1 = *(const float4*)&As[kk][tm + 4];
            float4 b0 = *(const float4*)&Bs[kk][tn];
            float4 b1 = *(const float4*)&Bs[kk][tn + 4];
            unsigned long long bb[4];
            bb[0] = pack2(b0.x, b0.y);
            bb[1] = pack2(b0.z, b0.w);
            bb[2] = pack2(b1.x, b1.y);
            bb[3] = pack2(b1.z, b1.w);
            float ra[8] = {a0.x, a0.y, a0.z, a0.w, a1.x, a1.y, a1.z, a1.w};
#pragma unroll
            for (int i = 0; i < 8; i++) {
                unsigned long long a2 = pack2(ra[i], ra[i]);
#pragma unroll
                for (int j = 0; j < 4; j++) fma2(c2[i][j], a2, bb[j]);
            }
        }
        __syncthreads();
    }

    // Epilogue: + bias, soma-bias transform on first half, store to g_emb.
    const int  ncol  = bn * BN + tn;             // global output column
    const bool is_sb = (ncol < MEM);             // uniform per block (BN | 1024)
    const float4 bs0 = *(const float4*)(bias + ncol);
    const float4 bs1 = *(const float4*)(bias + ncol + 4);
    const float bv[8] = {bs0.x, bs0.y, bs0.z, bs0.w, bs1.x, bs1.y, bs1.z, bs1.w};

#pragma unroll
    for (int i = 0; i < 8; i++) {
        int m = bm * BM + tm + i;
        float v[8];
#pragma unroll
        for (int j = 0; j < 4; j++) unpack2(c2[i][j], v[2 * j], v[2 * j + 1]);
#pragma unroll
        for (int e = 0; e < 8; e++) {
            v[e] += bv[e];
            if (is_sb) v[e] = 5.0f * tanhf(v[e] * 0.2f);
        }
        float* dst = g_emb + (size_t)m * NOUT + ncol;
        *(float4*)(dst)     = make_float4(v[0], v[1], v[2], v[3]);
        *(float4*)(dst + 4) = make_float4(v[4], v[5], v[6], v[7]);
    }
}

// ---------------------------------------------------------------------------
// Phase 2: sequential scan over L. One thread per (b, mem) state lane.
// out layout: h_t [B][L][MEM] followed by hf_last [B][MEM].
// ---------------------------------------------------------------------------
__global__ __launch_bounds__(256)
void scan_kernel(const float* __restrict__ h0, float* __restrict__ out)
{
    const int idx = blockIdx.x * 256 + threadIdx.x;   // 0 .. B*MEM-1
    const int b   = idx >> 10;
    const int mem = idx & (MEM - 1);

    float hf = h0[idx];                      // h0[0][b][mem]
    float hs = h0[B_DIM * MEM + idx];        // h0[1][b][mem]

    const float* e = g_emb + (size_t)b * L_DIM * NOUT + mem;
    float*       o = out   + (size_t)b * L_DIM * MEM  + mem;

#pragma unroll 4
    for (int l = 0; l < L_DIM; l++) {
        const float sb = e[(size_t)l * NOUT];
        const float io = e[(size_t)l * NOUT + MEM];

        const float hsb = hs + 0.4f;
        const float x   = io + 4.0f * hf - 7.0f * hsb * hsb + sb;
        const float hfn = tanhf(x);
        const float eps = 0.9f + 0.9f / (1.0f + expf(-(hf - 0.5f) * 10.0f));
        const float hsn = (1.0f - eps) * hs + eps * hf;

        o[(size_t)l * MEM] = hfn;
        hf = hfn;
        hs = hsn;
    }
    // hf_last
    out[(size_t)M_DIM * MEM + idx] = hf;
}

// ---------------------------------------------------------------------------
// Launch
// ---------------------------------------------------------------------------
extern "C" void kernel_launch(void* const* d_in, const int* in_sizes, int n_in,
                              void* d_out, int out_size)
{
    const float* u    = (const float*)d_in[0];   // (128, 512, 512)
    const float* h0   = (const float*)d_in[1];   // (2, 128, 1024)
    const float* W    = (const float*)d_in[2];   // (2048, 512)
    const float* bias = (const float*)d_in[3];   // (2048,)
    float* out = (float*)d_out;                  // h_t (128,512,1024) ++ hf_last (128,1024)

    dim3 grid(NOUT / BN, M_DIM / BM);            // (16, 512)
    gemm_emb_kernel<<<grid, 256>>>(u, W, bias);

    scan_kernel<<<(B_DIM * MEM) / 256, 256>>>(h0, out);
}

// round 3
// speedup vs baseline: 2.7805x; 2.7805x over previous
#include <cuda_runtime.h>
#include <cuda_bf16.h>
#include <cstdint>
#include <cstddef>

// ---------------------------------------------------------------------------
// Problem dims
// ---------------------------------------------------------------------------
#define B_DIM   128
#define L_DIM   512
#define IN_DIM  512
#define MEM     1024
#define NOUT    2048
#define M_DIM   (B_DIM * L_DIM)      // 65536

#define NCHUNK  24                   // K' = 1536 = 24 * 64
#define KC      64                   // bf16 cols per chunk (128B rows, SW128)

// ---------------------------------------------------------------------------
// Device scratch (static allocation — no runtime alloc)
// g_A2: [mt(512)][chunk(16)][128 rows][64 cols] bf16, SW128-swizzled 16KB blocks
//        chunks 0-7 = hi, 8-15 = lo
// g_W2: [nt(16)][chunk(16)][128 rows][64 cols] bf16, same layout
// ---------------------------------------------------------------------------
__device__ float          g_emb[(size_t)M_DIM * NOUT];          // 512 MB
__device__ __nv_bfloat16  g_A2[(size_t)M_DIM * 1024];           // 128 MB
__device__ __nv_bfloat16  g_W2[(size_t)NOUT * 1024];            // 4 MB

// ---------------------------------------------------------------------------
// Helpers
// ---------------------------------------------------------------------------
__device__ __forceinline__ uint32_t smem_u32(const void* p) {
    uint32_t a;
    asm("{ .reg .u64 t; cvta.to.shared.u64 t, %1; cvt.u32.u64 %0, t; }" : "=r"(a) : "l"(p));
    return a;
}
__device__ __forceinline__ uint32_t swz(uint32_t b) { return b ^ ((b >> 3) & 0x70); }

__device__ __forceinline__ void cp_async16(uint32_t dst, const void* src) {
    asm volatile("cp.async.cg.shared.global [%0], [%1], 16;" :: "r"(dst), "l"(src) : "memory");
}
__device__ __forceinline__ void cp_commit() {
    asm volatile("cp.async.commit_group;" ::: "memory");
}
template <int N>
__device__ __forceinline__ void cp_wait() {
    asm volatile("cp.async.wait_group %0;" :: "n"(N) : "memory");
}

#define LDSM4(r0, r1, r2, r3, a) \
    asm volatile("ldmatrix.sync.aligned.m8n8.x4.shared.b16 {%0,%1,%2,%3}, [%4];" \
                 : "=r"(r0), "=r"(r1), "=r"(r2), "=r"(r3) : "r"(a))

#define MMA16816(c0, c1, c2, c3, a0, a1, a2, a3, b0, b1) \
    asm volatile("mma.sync.aligned.m16n8k16.row.col.f32.bf16.bf16.f32 " \
                 "{%0,%1,%2,%3}, {%4,%5,%6,%7}, {%8,%9}, {%0,%1,%2,%3};" \
                 : "+f"(c0), "+f"(c1), "+f"(c2), "+f"(c3) \
                 : "r"(a0), "r"(a1), "r"(a2), "r"(a3), "r"(b0), "r"(b1))

// fast tanh / sigmoid (error ~1e-6, correctness threshold is 1e-3)
__device__ __forceinline__ float tanh_fast(float x) {
    float a = fabsf(x);
    float e = __expf(-2.0f * a);
    float r = __fdividef(1.0f - e, 1.0f + e);
    return copysignf(r, x);
}

// ---------------------------------------------------------------------------
// Conversion kernels: fp32 -> bf16 hi/lo, tiled + SW128 pre-swizzled blocks
// ---------------------------------------------------------------------------
__global__ __launch_bounds__(256) void conv_a_kernel(const float* __restrict__ u) {
    int idx = blockIdx.x * 256 + threadIdx.x;
    int m = idx >> 8;
    int k = (idx & 255) * 2;
    float2 v = *(const float2*)(u + (size_t)m * IN_DIM + k);
    __nv_bfloat16 h0 = __float2bfloat16(v.x);
    __nv_bfloat16 h1 = __float2bfloat16(v.y);
    __nv_bfloat16 l0 = __float2bfloat16(v.x - __bfloat162float(h0));
    __nv_bfloat16 l1 = __float2bfloat16(v.y - __bfloat162float(h1));
    uint32_t hp = (uint32_t)*(unsigned short*)&h0 | ((uint32_t)*(unsigned short*)&h1 << 16);
    uint32_t lp = (uint32_t)*(unsigned short*)&l0 | ((uint32_t)*(unsigned short*)&l1 << 16);
    int mt = m >> 7, r = m & 127;
    int ch = k >> 6, c = k & 63;
    uint32_t off = swz((uint32_t)(r * 128 + c * 2));
    char* base = (char*)g_A2;
    *(uint32_t*)(base + (((size_t)(mt * 16 + ch))     << 14) + off) = hp;
    *(uint32_t*)(base + (((size_t)(mt * 16 + 8 + ch)) << 14) + off) = lp;
}

__global__ __launch_bounds__(256) void conv_w_kernel(const float* __restrict__ W) {
    int idx = blockIdx.x * 256 + threadIdx.x;
    int n = idx >> 8;
    int k = (idx & 255) * 2;
    float2 v = *(const float2*)(W + (size_t)n * IN_DIM + k);
    __nv_bfloat16 h0 = __float2bfloat16(v.x);
    __nv_bfloat16 h1 = __float2bfloat16(v.y);
    __nv_bfloat16 l0 = __float2bfloat16(v.x - __bfloat162float(h0));
    __nv_bfloat16 l1 = __float2bfloat16(v.y - __bfloat162float(h1));
    uint32_t hp = (uint32_t)*(unsigned short*)&h0 | ((uint32_t)*(unsigned short*)&h1 << 16);
    uint32_t lp = (uint32_t)*(unsigned short*)&l0 | ((uint32_t)*(unsigned short*)&l1 << 16);
    int nt = n >> 7, r = n & 127;
    int ch = k >> 6, c = k & 63;
    uint32_t off = swz((uint32_t)(r * 128 + c * 2));
    char* base = (char*)g_W2;
    *(uint32_t*)(base + (((size_t)(nt * 16 + ch))     << 14) + off) = hp;
    *(uint32_t*)(base + (((size_t)(nt * 16 + 8 + ch)) << 14) + off) = lp;
}

// ---------------------------------------------------------------------------
// bf16 warp-MMA GEMM: C[m][n] = sum_{k'=0..1535} A''[m][k'] * W''[n][k']
// CTA tile 128x128, BK=64, 256 threads (8 warps, 2(m) x 4(n), warp tile 64x32).
// 3-stage cp.async pipeline. Grid (16, 512).
// ---------------------------------------------------------------------------
#define NST 3
#define STAGE_BYTES 32768                     // A 16KB + B 16KB
#define SMEM_TOTAL (NST * STAGE_BYTES)        // 96 KB

__global__ __launch_bounds__(256, 2) void gemm_mma_kernel(const float* __restrict__ bias) {
    extern __shared__ __align__(1024) char smem[];
    const uint32_t sm   = smem_u32(smem);
    const int tid  = threadIdx.x;
    const int wid  = tid >> 5;
    const int lane = tid & 31;
    const int nt   = blockIdx.x;     // 0..15
    const int mt   = blockIdx.y;     // 0..511
    const int wm   = wid >> 2;       // 0..1
    const int wn   = wid & 3;        // 0..3

    const char* Ab = (const char*)g_A2 + ((size_t)mt << 18);   // mt * 16 blocks * 16KB
    const char* Bb = (const char*)g_W2 + ((size_t)nt << 18);

    float acc[4][4][4];
#pragma unroll
    for (int i = 0; i < 4; i++)
#pragma unroll
        for (int j = 0; j < 4; j++)
#pragma unroll
            for (int e = 0; e < 4; e++) acc[i][j][e] = 0.0f;

    // ldmatrix per-lane addressing (SW128): phys_byte = r*128 + ((c16 ^ (r&7))*16)
    const int jj = lane >> 3;        // matrix index 0..3
    const int rl = lane & 7;         // row within 8x8 matrix; also r&7 for all frags
    uint32_t arow[4], brow[2];
#pragma unroll
    for (int mi = 0; mi < 4; mi++)
        arow[mi] = (uint32_t)((wm * 64 + mi * 16 + (jj & 1) * 8 + rl) * 128);
#pragma unroll
    for (int p = 0; p < 2; p++)
        brow[p] = (uint32_t)((wn * 32 + p * 16 + (jj & 1) * 8 + rl) * 128);

    auto load_stage = [&](int c, int s) {
        int ach = (c >= 16) ? (8 + c - 16) : (c & 7);   // A: [hi x8 | hi x8 | lo x8]
        int wch = (c >= 16) ? (c - 16)     : c;          // W: [hi x8 | lo x8 | hi x8]
        const char* As = Ab + ((size_t)ach << 14);
        const char* Bs = Bb + ((size_t)wch << 14);
        uint32_t dst = sm + (uint32_t)s * STAGE_BYTES;
#pragma unroll
        for (int i = 0; i < 4; i++) {
            uint32_t off = (uint32_t)(tid + i * 256) * 16;
            cp_async16(dst + off, As + off);
        }
#pragma unroll
        for (int i = 0; i < 4; i++) {
            uint32_t off = (uint32_t)(tid + i * 256) * 16;
            cp_async16(dst + 16384 + off, Bs + off);
        }
        cp_commit();
    };

    load_stage(0, 0);
    load_stage(1, 1);

    for (int ck = 0; ck < NCHUNK; ck++) {
        const int s = ck % NST;
        cp_wait<1>();
        __syncthreads();
        if (ck + 2 < NCHUNK) load_stage(ck + 2, (ck + 2) % NST);

        const uint32_t sA = sm + (uint32_t)s * STAGE_BYTES;
        const uint32_t sB = sA + 16384;

#pragma unroll
        for (int ks = 0; ks < 4; ks++) {
            const uint32_t cb = (uint32_t)(((2 * ks + (jj >> 1)) ^ rl) * 16);
            uint32_t a[4][4], br[2][4];
#pragma unroll
            for (int mi = 0; mi < 4; mi++)
                LDSM4(a[mi][0], a[mi][1], a[mi][2], a[mi][3], sA + arow[mi] + cb);
#pragma unroll
            for (int p = 0; p < 2; p++)
                LDSM4(br[p][0], br[p][1], br[p][2], br[p][3], sB + brow[p] + cb);
#pragma unroll
            for (int mi = 0; mi < 4; mi++) {
#pragma unroll
                for (int ni = 0; ni < 4; ni++) {
                    const int p = ni >> 1, sub = ni & 1;
                    MMA16816(acc[mi][ni][0], acc[mi][ni][1], acc[mi][ni][2], acc[mi][ni][3],
                             a[mi][0], a[mi][1], a[mi][2], a[mi][3],
                             br[p][sub], br[p][sub + 2]);
                }
            }
        }
    }

    // Epilogue: bias + soma-bias transform on first 1024 cols, store fp32
    const int  n0    = nt * 128;
    const bool is_sb = (nt < 8);
#pragma unroll
    for (int mi = 0; mi < 4; mi++) {
        const int row0 = mt * 128 + wm * 64 + mi * 16 + (lane >> 2);
#pragma unroll
        for (int ni = 0; ni < 4; ni++) {
            const int col = n0 + wn * 32 + ni * 8 + (lane & 3) * 2;
            const float2 b2 = *(const float2*)(bias + col);
            float v0 = acc[mi][ni][0] + b2.x;
            float v1 = acc[mi][ni][1] + b2.y;
            float v2 = acc[mi][ni][2] + b2.x;
            float v3 = acc[mi][ni][3] + b2.y;
            if (is_sb) {
                v0 = 5.0f * tanh_fast(v0 * 0.2f);
                v1 = 5.0f * tanh_fast(v1 * 0.2f);
                v2 = 5.0f * tanh_fast(v2 * 0.2f);
                v3 = 5.0f * tanh_fast(v3 * 0.2f);
            }
            *(float2*)&g_emb[(size_t)row0 * NOUT + col]       = make_float2(v0, v1);
            *(float2*)&g_emb[(size_t)(row0 + 8) * NOUT + col] = make_float2(v2, v3);
        }
    }
}

// ---------------------------------------------------------------------------
// Phase 2: sequential scan over L. One thread per (b, mem) lane.
// out layout: h_t [B][L][MEM] ++ hf_last [B][MEM]
// ---------------------------------------------------------------------------
__global__ __launch_bounds__(256) void scan_kernel(const float* __restrict__ h0,
                                                   float* __restrict__ out)
{
    const int idx = blockIdx.x * 256 + threadIdx.x;
    const int b   = idx >> 10;

    float hf = h0[idx];
    float hs = h0[B_DIM * MEM + idx];

    const float* e = g_emb + (size_t)b * L_DIM * NOUT + (idx & (MEM - 1));
    float*       o = out   + (size_t)b * L_DIM * MEM  + (idx & (MEM - 1));

#pragma unroll 4
    for (int l = 0; l < L_DIM; l++) {
        const float sb = e[(size_t)l * NOUT];
        const float io = e[(size_t)l * NOUT + MEM];

        const float hsb = hs + 0.4f;
        const float x   = io + 4.0f * hf - 7.0f * hsb * hsb + sb;
        const float hfn = tanh_fast(x);
        const float z   = (hf - 0.5f) * 10.0f;
        const float sig = __fdividef(1.0f, 1.0f + __expf(-z));
        const float eps = 0.9f + 0.9f * sig;
        const float hsn = (1.0f - eps) * hs + eps * hf;

        o[(size_t)l * MEM] = hfn;
        hf = hfn;
        hs = hsn;
    }
    out[(size_t)M_DIM * MEM + idx] = hf;
}

// ---------------------------------------------------------------------------
// Launch
// ---------------------------------------------------------------------------
extern "C" void kernel_launch(void* const* d_in, const int* in_sizes, int n_in,
                              void* d_out, int out_size)
{
    const float* u    = (const float*)d_in[0];   // (128, 512, 512)
    const float* h0   = (const float*)d_in[1];   // (2, 128, 1024)
    const float* W    = (const float*)d_in[2];   // (2048, 512)
    const float* bias = (const float*)d_in[3];   // (2048,)
    float* out = (float*)d_out;

    cudaFuncSetAttribute(gemm_mma_kernel, cudaFuncAttributeMaxDynamicSharedMemorySize, SMEM_TOTAL);

    conv_a_kernel<<<(M_DIM * IN_DIM / 2) / 256, 256>>>(u);   // 65536 blocks
    conv_w_kernel<<<(NOUT * IN_DIM / 2) / 256, 256>>>(W);    // 2048 blocks

    dim3 grid(16, 512);
    gemm_mma_kernel<<<grid, 256, SMEM_TOTAL>>>(bias);

    scan_kernel<<<(B_DIM * MEM) / 256, 256>>>(h0, out);
}